// round 1
// baseline (speedup 1.0000x reference)
#include <cuda_runtime.h>

// Intermediate y[k16][o8][h14][w14] from stage 1.
__device__ float g_y[16 * 8 * 14 * 14];

// Stage 1: y[k,o,h,w] = sum_{i=0..63, j=0..2} xr[i,o,h-1+j,w] * w1[k,i,j]
// where xr[.., hh, ..] = x[.., (hh-1) mod 14, ..] (roll by +1 along H),
// and taps outside hh in [0,14) are zero (zero pad on the rolled tensor).
__global__ void __launch_bounds__(256) stage1_kernel(
    const float* __restrict__ x,   // [512][14][14], channel c = i*8 + o
    const float* __restrict__ w1)  // [16][64][3]
{
    int t = blockIdx.x * blockDim.x + threadIdx.x;
    if (t >= 16 * 8 * 14 * 14) return;

    int w = t % 14;
    int h = (t / 14) % 14;
    int o = (t / 196) % 8;
    int k = t / 1568;            // warp-uniform: 1568 % 32 == 0

    // Per-tap source row and validity.
    bool v0, v1, v2;
    int b0, b1, b2;
    {
        int hh0 = h - 1, hh1 = h, hh2 = h + 1;
        v0 = (hh0 >= 0);
        v1 = true;
        v2 = (hh2 < 14);
        int r0 = (hh0 + 13) % 14;   // = (hh-1) mod 14
        int r1 = (hh1 + 13) % 14;
        int r2 = (hh2 + 13) % 14;
        b0 = r0 * 14 + w;
        b1 = r1 * 14 + w;
        b2 = r2 * 14 + w;
    }

    const float* __restrict__ w1k = w1 + k * 192;   // w1[k][.][.]

    float acc0 = 0.f, acc1 = 0.f, acc2 = 0.f;
    #pragma unroll 8
    for (int i = 0; i < 64; i++) {
        int cb = (i * 8 + o) * 196;
        float x0 = v0 ? __ldg(x + cb + b0) : 0.f;
        float x1 =      __ldg(x + cb + b1);
        float x2 = v2 ? __ldg(x + cb + b2) : 0.f;
        float a = __ldg(w1k + i * 3 + 0);
        float b = __ldg(w1k + i * 3 + 1);
        float c = __ldg(w1k + i * 3 + 2);
        acc0 = fmaf(x0, a, acc0);
        acc1 = fmaf(x1, b, acc1);
        acc2 = fmaf(x2, c, acc2);
    }
    g_y[t] = acc0 + acc1 + acc2;
}

// Stage 2: out[(i*16+k)*196 + h*14 + w] =
//   sum_{o=0..7, tap=0..2} y[k,o,h,w-1+tap] * w2[i,o,tap]   (zero pad along W)
__global__ void __launch_bounds__(256) stage2_kernel(
    const float* __restrict__ w2,  // [32][8][3]
    float* __restrict__ out)       // [512][14][14], channel = i*16 + k
{
    int t = blockIdx.x * blockDim.x + threadIdx.x;
    if (t >= 512 * 14 * 14) return;

    int w = t % 14;
    int h = (t / 14) % 14;
    int k = (t / 196) % 16;
    int i = t / 3136;             // warp-uniform: 3136 % 32 == 0

    const float* __restrict__ w2i = w2 + i * 24;

    bool vl = (w >= 1);
    bool vr = (w <= 12);

    float acc = 0.f;
    #pragma unroll
    for (int o = 0; o < 8; o++) {
        const float* __restrict__ yrow = g_y + (k * 8 + o) * 196 + h * 14;
        float y0 = vl ? yrow[w - 1] : 0.f;
        float y1 = yrow[w];
        float y2 = vr ? yrow[w + 1] : 0.f;
        float a = __ldg(w2i + o * 3 + 0);
        float b = __ldg(w2i + o * 3 + 1);
        float c = __ldg(w2i + o * 3 + 2);
        acc = fmaf(y0, a, acc);
        acc = fmaf(y1, b, acc);
        acc = fmaf(y2, c, acc);
    }
    out[t] = acc;
}

extern "C" void kernel_launch(void* const* d_in, const int* in_sizes, int n_in,
                              void* d_out, int out_size)
{
    const float* x  = (const float*)d_in[0];   // (1,512,14,14)
    const float* w1 = (const float*)d_in[1];   // (16,64,3)
    const float* w2 = (const float*)d_in[2];   // (32,8,3)
    float* out = (float*)d_out;                // (1,512,14,14)

    // Stage 1: 16*8*14*14 = 25088 outputs
    stage1_kernel<<<(25088 + 255) / 256, 256>>>(x, w1);
    // Stage 2: 512*14*14 = 100352 outputs (stream-ordered after stage 1)
    stage2_kernel<<<(100352 + 255) / 256, 256>>>(w2, out);
}